// round 6
// baseline (speedup 1.0000x reference)
#include <cuda_runtime.h>

#define BB   16
#define SEQ  512
#define NH   8
#define DH   128
#define HD   1024
#define NROWS (BB*SEQ)            // 8192
#define SCALE 0.08838834764831843f

// Scratch (no device allocation allowed)
__device__ float g_q  [BB*NH*SEQ*DH];  // [B,H,N,D] masked*scaled, tf32-rounded
__device__ float g_k  [BB*NH*SEQ*DH];  // [B,H,N,D] masked, tf32-rounded
__device__ float g_vt [BB*NH*DH*SEQ];  // [B,H,D,N] masked V TRANSPOSED, tf32
__device__ float g_y1 [NROWS*HD];      // [B,N,H*D] attn out, tf32-rounded
__device__ float g_xr [NROWS*DH];      // x rounded
__device__ float g_wqt[HD*DH];         // Wq^T [n][k], rounded
__device__ float g_wkt[HD*DH];
__device__ float g_wvt[HD*DH];
__device__ float g_wot[DH*HD];         // Wo^T [n=128][k=1024], rounded

__device__ __forceinline__ unsigned f2tf(float f) {
    unsigned u;
    asm("cvt.rna.tf32.f32 %0, %1;" : "=r"(u) : "f"(f));
    return u;
}
__device__ __forceinline__ float rtf(float f) { return __uint_as_float(f2tf(f)); }

__device__ __forceinline__ void cpa16(void* dst_smem, const void* src_gmem) {
    unsigned s = (unsigned)__cvta_generic_to_shared(dst_smem);
    asm volatile("cp.async.cg.shared.global [%0], [%1], 16;\n" :: "r"(s), "l"(src_gmem));
}
#define CP_COMMIT() asm volatile("cp.async.commit_group;\n")
#define CP_WAIT(n)  asm volatile("cp.async.wait_group %0;\n" :: "n"(n))

__device__ __forceinline__ unsigned smaddr(const void* p) {
    return (unsigned)__cvta_generic_to_shared(p);
}
// one LDSM.x4: four 8-row x 16B matrices (tf32 8x4 blocks)
__device__ __forceinline__ void ldsm4(unsigned* r, unsigned a) {
    asm volatile("ldmatrix.sync.aligned.m8n8.x4.shared.b16 {%0,%1,%2,%3}, [%4];"
        : "=r"(r[0]), "=r"(r[1]), "=r"(r[2]), "=r"(r[3]) : "r"(a));
}

// D (4xf32) += A(16x8 tf32) @ B(8x8 tf32)
__device__ __forceinline__ void mma8(float* d, const unsigned* a, const unsigned* b) {
    asm volatile(
        "mma.sync.aligned.m16n8k8.row.col.f32.tf32.tf32.f32 "
        "{%0,%1,%2,%3}, {%4,%5,%6,%7}, {%8,%9}, {%0,%1,%2,%3};"
        : "+f"(d[0]), "+f"(d[1]), "+f"(d[2]), "+f"(d[3])
        : "r"(a[0]), "r"(a[1]), "r"(a[2]), "r"(a[3]), "r"(b[0]), "r"(b[1]));
}

// ---------------------------------------------------------------------------
// prep: round x. grid 1024 x 256
// ---------------------------------------------------------------------------
__global__ void prep_kernel(const float* __restrict__ x)
{
    int i = blockIdx.x * 256 + threadIdx.x;       // float4 index
    if (i < NROWS*DH/4) {
        float4 v = ((const float4*)x)[i];
        ((float4*)g_xr)[i] = make_float4(rtf(v.x), rtf(v.y), rtf(v.z), rtf(v.w));
    }
}

// ---------------------------------------------------------------------------
// weight transpose + round: W[R][C] -> Wt[C][R].  grid (32,32,4), block (32,8)
// ---------------------------------------------------------------------------
__global__ void wtrans_kernel(const float* __restrict__ Wq, const float* __restrict__ Wk,
                              const float* __restrict__ Wv, const float* __restrict__ Wo)
{
    __shared__ float t[32][33];
    const int z = blockIdx.z;
    const float* src = (z == 0) ? Wq : (z == 1) ? Wk : (z == 2) ? Wv : Wo;
    float* dst = (z == 0) ? g_wqt : (z == 1) ? g_wkt : (z == 2) ? g_wvt : g_wot;
    const int R = (z < 3) ? DH : HD;      // src rows (k)
    const int C = (z < 3) ? HD : DH;      // src cols (n)
    if ((int)blockIdx.x * 32 >= C || (int)blockIdx.y * 32 >= R) return;
    const int tx = threadIdx.x, ty = threadIdx.y;
    const int r = blockIdx.y * 32, c = blockIdx.x * 32;
#pragma unroll
    for (int j = 0; j < 4; j++)
        t[ty + j*8][tx] = rtf(src[(size_t)(r + ty + j*8) * C + c + tx]);
    __syncthreads();
#pragma unroll
    for (int j = 0; j < 4; j++)
        dst[(size_t)(c + ty + j*8) * R + r + tx] = t[tx][ty + j*8];
}

// ---------------------------------------------------------------------------
// QKV projection: out = (x @ W + b) * mask (* scale for q) -> [B,H,N,D] (tf32)
// (V written transposed -> g_vt [B,H,D,N])
// grid (HD/128, NROWS/128, 3), 256 thr; tile 128x128, K staged 32, double-buf
// smem/stage: As [128][36] + Bs(Wt) [128][36] = 9216 words
// ---------------------------------------------------------------------------
#define PROJ_STG 9216
__global__ __launch_bounds__(256, 2) void proj_kernel(
    const float* __restrict__ mask,
    const float* __restrict__ bq, const float* __restrict__ bk,
    const float* __restrict__ bv)
{
    extern __shared__ unsigned sm[];
    const int tid = threadIdx.x;
    const int wid = tid >> 5, lane = tid & 31;
    const int g = lane >> 2, c = lane & 3;
    const int lr = lane & 7, lsel = (lane >> 3) & 1, lhi = lane >> 4;
    const int wm = wid & 3, wn = wid >> 2;       // warp tile 32 x 64
    const int c0 = blockIdx.x * 128;
    const int r0 = blockIdx.y * 128;
    const int sel = blockIdx.z;
    const float* Wt   = (sel == 0) ? g_wqt : (sel == 1) ? g_wkt : g_wvt;
    const float* bias = (sel == 0) ? bq : (sel == 1) ? bk : bv;
    const float extra = (sel == 0) ? SCALE : 1.0f;
    const float* xbase = g_xr + (size_t)r0 * DH;

    const int arow = tid >> 3, aq = (tid & 7) * 4;
#define PROJ_FILL(ks, buf) {                                                    \
        unsigned* As = sm + (buf) * PROJ_STG;                                   \
        unsigned* Bs = As + 4608;                                               \
        const int k0 = (ks) * 32;                                               \
        _Pragma("unroll")                                                       \
        for (int t = 0; t < 4; t++) {                                           \
            int row = arow + t * 32;                                            \
            cpa16(&As[row * 36 + aq], &xbase[(size_t)row * DH + k0 + aq]);      \
            cpa16(&Bs[row * 36 + aq], &Wt[(size_t)(c0 + row) * DH + k0 + aq]);  \
        }                                                                       \
        CP_COMMIT(); }

    float acc[2][8][4];
#pragma unroll
    for (int mf = 0; mf < 2; mf++)
#pragma unroll
        for (int nf = 0; nf < 8; nf++)
#pragma unroll
            for (int i = 0; i < 4; i++) acc[mf][nf][i] = 0.0f;

    PROJ_FILL(0, 0);
    for (int ks = 0; ks < 4; ks++) {
        if (ks < 3) { PROJ_FILL(ks + 1, (ks + 1) & 1); CP_WAIT(1); }
        else        { CP_WAIT(0); }
        __syncthreads();
        const unsigned* As = sm + (ks & 1) * PROJ_STG;
        const unsigned* Bs = As + 4608;
        unsigned aA[2], bB[4];
#pragma unroll
        for (int mf = 0; mf < 2; mf++)
            aA[mf] = smaddr(&As[(wm*32 + mf*16 + lr + 8*lsel) * 36 + 4*lhi]);
#pragma unroll
        for (int p = 0; p < 4; p++)
            bB[p] = smaddr(&Bs[(wn*64 + p*16 + lr + 8*lhi) * 36 + 4*lsel]);
#pragma unroll
        for (int kb = 0; kb < 4; kb++) {
            unsigned a0[4], a1[4];
            ldsm4(a0, aA[0] + kb*32);
            ldsm4(a1, aA[1] + kb*32);
#pragma unroll
            for (int p = 0; p < 4; p++) {
                unsigned bb[4];
                ldsm4(bb, bB[p] + kb*32);
                mma8(acc[0][2*p],   a0, bb);
                mma8(acc[0][2*p+1], a0, bb + 2);
                mma8(acc[1][2*p],   a1, bb);
                mma8(acc[1][2*p+1], a1, bb + 2);
            }
        }
        __syncthreads();
    }

    // epilogue: (acc + bias) * mask(*scale), tf32-round; V scattered transposed
#pragma unroll
    for (int mf = 0; mf < 2; mf++) {
#pragma unroll
        for (int rr = 0; rr < 2; rr++) {
            int row = r0 + wm * 32 + mf * 16 + g + rr * 8;
            int bI = row >> 9, n = row & 511;
            float mm = mask[row] * extra;
#pragma unroll
            for (int nf = 0; nf < 8; nf++) {
                int col = c0 + wn * 64 + nf * 8 + 2 * c;
                int h = col >> 7, d = col & 127;
                float v0 = rtf((acc[mf][nf][rr * 2 + 0] + bias[col]) * mm);
                float v1 = rtf((acc[mf][nf][rr * 2 + 1] + bias[col + 1]) * mm);
                if (sel == 2) {
                    float* p = g_vt + (((size_t)bI * NH + h) * DH + d) * SEQ + n;
                    p[0] = v0; p[SEQ] = v1;
                } else {
                    float* out = (sel == 0) ? g_q : g_k;
                    *(float2*)&out[(((size_t)bI * NH + h) * SEQ + n) * DH + d] =
                        make_float2(v0, v1);
                }
            }
        }
    }
}

// ---------------------------------------------------------------------------
// Flash attention, no-max softmax. LDSM fragment loads everywhere.
// grid (SEQ/128, BB*NH), 512 thr: 16 warps = 8 row-groups x 2 col-halves.
// smem: Qs[128][132] Ks[64][132] VsT[128][68] Ps[128][68] Msa[512] Lp[256]
// ---------------------------------------------------------------------------
__global__ __launch_bounds__(512, 1) void attn_kernel(
    const float* __restrict__ dist, const float* __restrict__ mask)
{
    extern __shared__ unsigned smu[];
    unsigned* Qs  = smu;                   // 16896
    unsigned* Ks  = Qs + 16896;            //  8448
    unsigned* VsT = Ks + 8448;             //  8704  [d][key] stride 68
    unsigned* Ps  = VsT + 8704;            //  8704  [row][key] stride 68
    float*    Msa = (float*)(Ps + 8704);   //   512 additive mask
    float*    Lp  = Msa + 512;             //   256 l partials

    const int tid = threadIdx.x;
    const int wid = tid >> 5, lane = tid & 31;
    const int g = lane >> 2, c = lane & 3;
    const int lr = lane & 7, lsel = (lane >> 3) & 1, lhi = lane >> 4;
    const int wm = wid & 7, wn = wid >> 3;   // 8 row-groups x 2 col-halves
    const int bh = blockIdx.y;
    const int b = bh >> 3, h = bh & 7;
    const int q0 = blockIdx.x * 128;
    const int m0 = wm * 16;

    const float* qbase  = g_q  + (size_t)bh * SEQ * DH;
    const float* kbase  = g_k  + (size_t)bh * SEQ * DH;
    const float* vtbase = g_vt + (size_t)bh * DH * SEQ;

    const int frow = tid >> 5, fq = (tid & 31) * 4;   // Q/K fill coords

#define FILL_K(kt) {                                                            \
        _Pragma("unroll")                                                       \
        for (int t = 0; t < 4; t++) {                                           \
            int key = frow + t * 16;                                            \
            cpa16(&Ks[key * 132 + fq],                                          \
                  &kbase[(size_t)((kt) * 64 + key) * DH + fq]);                 \
        }                                                                       \
        CP_COMMIT(); }
// V tile: [d=128][key 64] from g_vt rows
#define FILL_V(kt) {                                                            \
        _Pragma("unroll")                                                       \
        for (int t = 0; t < 4; t++) {                                           \
            int i = tid + t * 512;                                              \
            int d = i >> 4, kq = (i & 15) * 4;                                  \
            cpa16(&VsT[d * 68 + kq],                                            \
                  &vtbase[(size_t)d * SEQ + (kt) * 64 + kq]);                   \
        }                                                                       \
        CP_COMMIT(); }

    // prologue
    {
#pragma unroll
        for (int t = 0; t < 8; t++) {
            int row = frow + t * 16;
            cpa16(&Qs[row * 132 + fq], &qbase[(size_t)(q0 + row) * DH + fq]);
        }
#pragma unroll
        for (int t = 0; t < 4; t++) {
            int key = frow + t * 16;
            cpa16(&Ks[key * 132 + fq], &kbase[(size_t)key * DH + fq]);
        }
        CP_COMMIT();
        FILL_V(0);
        Msa[tid] = (mask[b * SEQ + tid] == 0.0f) ? -1e9f : 0.0f;
    }

    float O[8][4];
#pragma unroll
    for (int nf = 0; nf < 8; nf++)
#pragma unroll
        for (int i = 0; i < 4; i++) O[nf][i] = 0.0f;
    float l_t[2] = {0.0f, 0.0f};

    const unsigned aQ  = smaddr(&Qs[(m0 + lr + 8*lsel) * 132 + 4*lhi]);
    const unsigned bK0 = smaddr(&Ks[(wn*32 + lr + 8*lhi) * 132 + 4*lsel]);
    const unsigned bK1 = bK0 + 16 * 132 * 4;
    const unsigned aP  = smaddr(&Ps[(m0 + lr + 8*lsel) * 68 + 4*lhi]);
    const unsigned bV  = smaddr(&VsT[(wn*64 + lr + 8*lhi) * 68 + 4*lsel]);

    for (int kt = 0; kt < 8; kt++) {
        const int k0 = kt * 64;
        CP_WAIT(1);                       // K(kt) (and Q, Msa) ready
        __syncthreads();

        // S = Q @ K^T : 16 rows x 32 keys (this wn half)
        float s[4][4];
#pragma unroll
        for (int nf = 0; nf < 4; nf++)
#pragma unroll
            for (int i = 0; i < 4; i++) s[nf][i] = 0.0f;
#pragma unroll
        for (int kb = 0; kb < 16; kb++) {
            unsigned a[4], b0[4], b1[4];
            ldsm4(a,  aQ  + kb*32);
            ldsm4(b0, bK0 + kb*32);
            ldsm4(b1, bK1 + kb*32);
            mma8(s[0], a, b0); mma8(s[1], a, b0 + 2);
            mma8(s[2], a, b1); mma8(s[3], a, b1 + 2);
        }
        __syncthreads();                  // Ks fully consumed
        if (kt < 7) FILL_K(kt + 1);       // overlaps softmax + PV

        // softmax (no max-tracking): p = exp(s + dist + madd); accumulate l
#pragma unroll
        for (int rr = 0; rr < 2; rr++) {
            const int n = q0 + m0 + g + rr * 8;
            const float* drow = &dist[((size_t)b * SEQ + n) * SEQ + k0 + wn * 32];
#pragma unroll
            for (int nf = 0; nf < 4; nf++) {
                int col = nf * 8 + 2 * c;            // within 32-key half
                int gcol = wn * 32 + col;            // within 64-key tile
                float2 dv = *(const float2*)&drow[col];
                float s0 = s[nf][rr * 2 + 0] + dv.x + Msa[k0 + gcol];
                float s1 = s[nf][rr * 2 + 1] + dv.y + Msa[k0 + gcol + 1];
                float p0 = __expf(s0);
                float p1 = __expf(s1);
                l_t[rr] += p0 + p1;
                *(uint2*)&Ps[(m0 + g + rr * 8) * 68 + gcol] =
                    make_uint2(f2tf(p0), f2tf(p1));
            }
        }
        if (kt < 7) CP_WAIT(1); else CP_WAIT(0);   // V(kt) ready
        __syncthreads();                  // Ps complete + VsT ready

        // O += P @ V : 16 rows x 64 D-cols (this wn half), k = 64
#pragma unroll
        for (int kb = 0; kb < 8; kb++) {
            unsigned a[4];
            ldsm4(a, aP + kb*32);
#pragma unroll
            for (int t = 0; t < 4; t++) {
                unsigned bb[4];
                ldsm4(bb, bV + t * (16*68*4) + kb*32);
                mma8(O[2*t],     a, bb);
                mma8(O[2*t + 1], a, bb + 2);
            }
        }
        __syncthreads();                  // VsT + Ps consumed
        if (kt < 7) FILL_V(kt + 1);       // overlaps next S-MMA
    }

    // final l reduction
#pragma unroll
    for (int rr = 0; rr < 2; rr++) {
        float lv = l_t[rr];
        lv += __shfl_xor_sync(0xffffffffu, lv, 1);
        lv += __shfl_xor_sync(0xffffffffu, lv, 2);
        if (c == 0) Lp[wn * 128 + m0 + g + rr * 8] = lv;
    }
    __syncthreads();

#pragma unroll
    for (int rr = 0; rr < 2; rr++) {
        int row = m0 + g + rr * 8;
        float l = Lp[row] + Lp[128 + row];
        float inv = (l > 0.0f) ? 1.0f / l : 0.0f;
        float* orow = g_y1 + ((size_t)b * SEQ + q0 + row) * HD + h * DH + wn * 64;
#pragma unroll
        for (int nf = 0; nf < 8; nf++) {
            int col = nf * 8 + 2 * c;
            *(float2*)&orow[col] = make_float2(rtf(O[nf][rr * 2 + 0] * inv),
                                               rtf(O[nf][rr * 2 + 1] * inv));
        }
    }
}

// ---------------------------------------------------------------------------
// Output projection: out = (y1 @ Wo + bo) * mask
// grid NROWS/32 = 256, 256 thr (wm 0..1 x 16 rows, wn 0..3 x 32 cols)
// K staged 64, double-buffered: As[32][68] + Bs(Wot)[128][68] per stage
// ---------------------------------------------------------------------------
#define OP_STG 10880
__global__ __launch_bounds__(256, 2) void oproj_kernel(
    const float* __restrict__ bo, const float* __restrict__ mask,
    float* __restrict__ out)
{
    extern __shared__ unsigned sm[];
    const int tid = threadIdx.x;
    const int wid = tid >> 5, lane = tid & 31;
    const int g = lane >> 2, c = lane & 3;
    const int lr = lane & 7, lsel = (lane >> 3) & 1, lhi = lane >> 4;
    const int wm = wid & 1, wn = wid >> 1;      // warp tile 16 x 32
    const int r0 = blockIdx.x * 32;
    const float* abase = g_y1 + (size_t)r0 * HD;

    const int arow = tid >> 4, aq = (tid & 15) * 4;  // A: 2 chunks/thread
    const int brow = tid >> 4, bq_ = (tid & 15) * 4; // B: 8 chunks/thread
#define OP_FILL(ks, buf) {                                                      \
        unsigned* As = sm + (buf) * OP_STG;                                     \
        unsigned* Bs = As + 2176;                                               \
        const int k0 = (ks) * 64;                                               \
        _Pragma("unroll")                                                       \
        for (int t = 0; t < 2; t++) {                                           \
            int row = arow + t * 16;                                            \
            cpa16(&As[row * 68 + aq], &abase[(size_t)row * HD + k0 + aq]);      \
        }                                                                       \
        _Pragma("unroll")                                                       \
        for (int t = 0; t < 8; t++) {                                           \
            int row = brow + t * 16;                                            \
            cpa16(&Bs[row * 68 + bq_], &g_wot[(size_t)row * HD + k0 + bq_]);    \
        }                                                                       \
        CP_COMMIT(); }

    float acc[4][4];
#pragma unroll
    for (int nf = 0; nf < 4; nf++)
#pragma unroll
        for (int i = 0; i < 4; i++) acc[nf][i] = 0.0f;

    OP_FILL(0, 0);
    for (int ks = 0; ks < 16; ks++) {
        if (ks < 15) { OP_FILL(ks + 1, (ks + 1) & 1); CP_WAIT(1); }
        else         { CP_WAIT(0); }
        __syncthreads();
        const unsigned* As = sm + (ks & 1) * OP_STG;
        const unsigned* Bs = As + 2176;
        unsigned aA = smaddr(&As[(wm*16 + lr + 8*lsel) * 68 + 4*lhi]);
        unsigned bB[2];
#pragma unroll
        for (int p = 0; p < 2; p++)
            bB[p] = smaddr(&Bs[(wn*32 + p*16 + lr + 8*lhi) * 68 + 4*lsel]);
#pragma unroll
        for (int kb = 0; kb < 8; kb++) {
            unsigned a[4];
            ldsm4(a, aA + kb*32);
#pragma unroll
            for (int p = 0; p < 2; p++) {
                unsigned bb[4];
                ldsm4(bb, bB[p] + kb*32);
                mma8(acc[2*p],     a, bb);
                mma8(acc[2*p + 1], a, bb + 2);
            }
        }
        __syncthreads();
    }

#pragma unroll
    for (int rr = 0; rr < 2; rr++) {
        int row = r0 + wm * 16 + g + rr * 8;
        float mm = mask[row];
#pragma unroll
        for (int nf = 0; nf < 4; nf++) {
            int col = wn * 32 + nf * 8 + 2 * c;
            float v0 = (acc[nf][rr * 2 + 0] + bo[col]) * mm;
            float v1 = (acc[nf][rr * 2 + 1] + bo[col + 1]) * mm;
            *(float2*)&out[(size_t)row * DH + col] = make_float2(v0, v1);
        }
    }
}

// ---------------------------------------------------------------------------
extern "C" void kernel_launch(void* const* d_in, const int* in_sizes, int n_in,
                              void* d_out, int out_size)
{
    const float* x    = (const float*)d_in[0];
    const float* dist = (const float*)d_in[1];
    const float* mask = (const float*)d_in[2];
    const float* Wq   = (const float*)d_in[3];
    const float* bq   = (const float*)d_in[4];
    const float* Wk   = (const float*)d_in[5];
    const float* bk   = (const float*)d_in[6];
    const float* Wv   = (const float*)d_in[7];
    const float* bv   = (const float*)d_in[8];
    const float* Wo   = (const float*)d_in[9];
    const float* bo   = (const float*)d_in[10];
    float* out = (float*)d_out;

    const int proj_smem = PROJ_STG * 2 * 4;                             // 73728
    const int attn_smem = (16896 + 8448 + 8704 + 8704 + 512 + 256) * 4; // 174080
    const int op_smem   = OP_STG * 2 * 4;                               // 87040
    static int configured = 0;
    if (!configured) {
        cudaFuncSetAttribute(proj_kernel, cudaFuncAttributeMaxDynamicSharedMemorySize, proj_smem);
        cudaFuncSetAttribute(attn_kernel, cudaFuncAttributeMaxDynamicSharedMemorySize, attn_smem);
        cudaFuncSetAttribute(oproj_kernel, cudaFuncAttributeMaxDynamicSharedMemorySize, op_smem);
        configured = 1;
    }

    prep_kernel<<<1024, 256>>>(x);
    wtrans_kernel<<<dim3(32, 32, 4), dim3(32, 8)>>>(Wq, Wk, Wv, Wo);
    proj_kernel<<<dim3(HD/128, NROWS/128, 3), 256, proj_smem>>>(mask, bq, bk, bv);
    attn_kernel<<<dim3(SEQ/128, BB*NH), 512, attn_smem>>>(dist, mask);
    oproj_kernel<<<dim3(NROWS/32), 256, op_smem>>>(bo, mask, out);
}

// round 7
// speedup vs baseline: 1.5987x; 1.5987x over previous
#include <cuda_runtime.h>

#define BB   16
#define SEQ  512
#define NH   8
#define DH   128
#define HD   1024
#define NROWS (BB*SEQ)            // 8192
#define SCALE 0.08838834764831843f

// Scratch (no device allocation allowed)
__device__ float g_q [BB*NH*SEQ*DH];   // [B,H,N,D] masked*scaled, tf32-rounded
__device__ float g_k [BB*NH*SEQ*DH];   // [B,H,N,D] masked, tf32-rounded
__device__ float g_v [BB*NH*SEQ*DH];   // [B,H,N,D] masked, tf32-rounded
__device__ float g_y1[NROWS*HD];       // [B,N,H*D] attn out, tf32-rounded
__device__ float g_xr[NROWS*DH];       // x rounded
__device__ float g_wq[DH*HD], g_wk[DH*HD], g_wv[DH*HD], g_wo[HD*DH];

__device__ __forceinline__ unsigned f2tf(float f) {
    unsigned u;
    asm("cvt.rna.tf32.f32 %0, %1;" : "=r"(u) : "f"(f));
    return u;
}
__device__ __forceinline__ float rtf(float f) { return __uint_as_float(f2tf(f)); }

__device__ __forceinline__ void cpa16(void* dst_smem, const void* src_gmem) {
    unsigned s = (unsigned)__cvta_generic_to_shared(dst_smem);
    asm volatile("cp.async.cg.shared.global [%0], [%1], 16;\n" :: "r"(s), "l"(src_gmem));
}
#define CP_COMMIT() asm volatile("cp.async.commit_group;\n")
#define CP_WAIT(n)  asm volatile("cp.async.wait_group %0;\n" :: "n"(n))

// D (4xf32) += A(16x8 tf32) @ B(8x8 tf32)
__device__ __forceinline__ void mma8(float* d, const unsigned* a, const unsigned* b) {
    asm volatile(
        "mma.sync.aligned.m16n8k8.row.col.f32.tf32.tf32.f32 "
        "{%0,%1,%2,%3}, {%4,%5,%6,%7}, {%8,%9}, {%0,%1,%2,%3};"
        : "+f"(d[0]), "+f"(d[1]), "+f"(d[2]), "+f"(d[3])
        : "r"(a[0]), "r"(a[1]), "r"(a[2]), "r"(a[3]), "r"(b[0]), "r"(b[1]));
}

// ---------------------------------------------------------------------------
// prep: round x + weights to tf32 (into scratch). grid 1024 x 256
// ---------------------------------------------------------------------------
__global__ void prep_kernel(const float* __restrict__ x,
                            const float* __restrict__ Wq, const float* __restrict__ Wk,
                            const float* __restrict__ Wv, const float* __restrict__ Wo)
{
    int i = blockIdx.x * 256 + threadIdx.x;       // float4 index
    if (i < NROWS*DH/4) {
        float4 v = ((const float4*)x)[i];
        ((float4*)g_xr)[i] = make_float4(rtf(v.x), rtf(v.y), rtf(v.z), rtf(v.w));
    }
    if (i < DH*HD/4) {
        float4 a = ((const float4*)Wq)[i];
        ((float4*)g_wq)[i] = make_float4(rtf(a.x), rtf(a.y), rtf(a.z), rtf(a.w));
        float4 b = ((const float4*)Wk)[i];
        ((float4*)g_wk)[i] = make_float4(rtf(b.x), rtf(b.y), rtf(b.z), rtf(b.w));
        float4 c = ((const float4*)Wv)[i];
        ((float4*)g_wv)[i] = make_float4(rtf(c.x), rtf(c.y), rtf(c.z), rtf(c.w));
        float4 d = ((const float4*)Wo)[i];
        ((float4*)g_wo)[i] = make_float4(rtf(d.x), rtf(d.y), rtf(d.z), rtf(d.w));
    }
}

// ---------------------------------------------------------------------------
// QKV projection: out = (x @ W + b) * mask (* scale for q) -> [B,H,N,D] (tf32)
// grid (HD/128, NROWS/128, 3), 256 thr; tile 128x128, K staged 32, double-buf
// ---------------------------------------------------------------------------
#define PROJ_STG 8960
__global__ __launch_bounds__(256, 2) void proj_kernel(
    const float* __restrict__ mask,
    const float* __restrict__ bq, const float* __restrict__ bk,
    const float* __restrict__ bv)
{
    extern __shared__ unsigned sm[];
    const int tid = threadIdx.x;
    const int wid = tid >> 5, lane = tid & 31;
    const int g = lane >> 2, c = lane & 3;
    const int wm = wid & 3, wn = wid >> 2;       // warp tile 32 x 64
    const int c0 = blockIdx.x * 128;
    const int r0 = blockIdx.y * 128;
    const int sel = blockIdx.z;
    const float* W    = (sel == 0) ? g_wq : (sel == 1) ? g_wk : g_wv;
    const float* bias = (sel == 0) ? bq : (sel == 1) ? bk : bv;
    float*       out  = (sel == 0) ? g_q : (sel == 1) ? g_k : g_v;
    const float extra = (sel == 0) ? SCALE : 1.0f;
    const float* xbase = g_xr + (size_t)r0 * DH;

    const int arow = tid >> 3, aq = (tid & 7) * 4;
    const int bkk = tid >> 5, bq_ = (tid & 31) * 4;
#define PROJ_FILL(ks, buf) {                                                   \
        unsigned* As = sm + (buf) * PROJ_STG;                                  \
        unsigned* Bs = As + 4608;                                              \
        const int k0 = (ks) * 32;                                              \
        _Pragma("unroll")                                                      \
        for (int t = 0; t < 4; t++) {                                          \
            int row = arow + t * 32;                                           \
            cpa16(&As[row * 36 + aq], &xbase[(size_t)row * DH + k0 + aq]);     \
        }                                                                      \
        _Pragma("unroll")                                                      \
        for (int t = 0; t < 4; t++) {                                          \
            int kk = bkk + t * 8;                                              \
            cpa16(&Bs[kk * 136 + bq_], &W[(size_t)(k0 + kk) * HD + c0 + bq_]); \
        }                                                                      \
        CP_COMMIT(); }

    float acc[2][8][4];
#pragma unroll
    for (int mf = 0; mf < 2; mf++)
#pragma unroll
        for (int nf = 0; nf < 8; nf++)
#pragma unroll
            for (int i = 0; i < 4; i++) acc[mf][nf][i] = 0.0f;

    PROJ_FILL(0, 0);
    for (int ks = 0; ks < 4; ks++) {
        if (ks < 3) { PROJ_FILL(ks + 1, (ks + 1) & 1); CP_WAIT(1); }
        else        { CP_WAIT(0); }
        __syncthreads();
        const unsigned* As = sm + (ks & 1) * PROJ_STG;
        const unsigned* Bs = As + 4608;
#pragma unroll
        for (int kb = 0; kb < 4; kb++) {
            const int k8 = kb * 8;
            unsigned a[2][4];
#pragma unroll
            for (int mf = 0; mf < 2; mf++) {
                int row = wm * 32 + mf * 16;
                a[mf][0] = As[(row + g) * 36 + k8 + c];
                a[mf][1] = As[(row + g + 8) * 36 + k8 + c];
                a[mf][2] = As[(row + g) * 36 + k8 + c + 4];
                a[mf][3] = As[(row + g + 8) * 36 + k8 + c + 4];
            }
#pragma unroll
            for (int nf = 0; nf < 8; nf++) {
                int col = wn * 64 + nf * 8;
                unsigned b[2];
                b[0] = Bs[(k8 + c) * 136 + col + g];
                b[1] = Bs[(k8 + c + 4) * 136 + col + g];
                mma8(acc[0][nf], a[0], b);
                mma8(acc[1][nf], a[1], b);
            }
        }
        __syncthreads();
    }

#pragma unroll
    for (int mf = 0; mf < 2; mf++) {
#pragma unroll
        for (int rr = 0; rr < 2; rr++) {
            int row = r0 + wm * 32 + mf * 16 + g + rr * 8;
            int bI = row >> 9, n = row & 511;
            float mm = mask[row] * extra;
#pragma unroll
            for (int nf = 0; nf < 8; nf++) {
                int col = c0 + wn * 64 + nf * 8 + 2 * c;
                int h = col >> 7, d = col & 127;
                float v0 = rtf((acc[mf][nf][rr * 2 + 0] + bias[col]) * mm);
                float v1 = rtf((acc[mf][nf][rr * 2 + 1] + bias[col + 1]) * mm);
                *(float2*)&out[(((size_t)bI * NH + h) * SEQ + n) * DH + d] =
                    make_float2(v0, v1);
            }
        }
    }
}

// ---------------------------------------------------------------------------
// Flash attention, no-max softmax, dist tile PREFETCHED to smem via cp.async.
// grid (SEQ/128, BB*NH), 512 thr: 16 warps = 8 row-groups x 2 col-halves.
// smem: Qs[128][132] Ks[64][132] Vs[64][136] Ps[128][68] Ds[128][68]
//       Msa[512] Lp[256]   => 52224 words = 208896 B
// Commit-group schedule per kt: enter with [K+D](kt) done, [V](kt) pending.
// ---------------------------------------------------------------------------
__global__ __launch_bounds__(512, 1) void attn_kernel(
    const float* __restrict__ dist, const float* __restrict__ mask)
{
    extern __shared__ unsigned smu[];
    unsigned* Qs  = smu;                   // 16896
    unsigned* Ks  = Qs + 16896;            //  8448
    unsigned* Vs  = Ks + 8448;             //  8704
    unsigned* Ps  = Vs + 8704;             //  8704
    float*    Ds  = (float*)(Ps + 8704);   //  8704  [row][64] stride 68
    float*    Msa = Ds + 8704;             //   512 additive mask
    float*    Lp  = Msa + 512;             //   256 l partials

    const int tid = threadIdx.x;
    const int wid = tid >> 5, lane = tid & 31;
    const int g = lane >> 2, c = lane & 3;
    const int wm = wid & 7, wn = wid >> 3;   // 8 row-groups x 2 col-halves
    const int bh = blockIdx.y;
    const int b = bh >> 3, h = bh & 7;
    const int q0 = blockIdx.x * 128;
    const int m0 = wm * 16;

    const float* qbase = g_q + (size_t)bh * SEQ * DH;
    const float* kbase = g_k + (size_t)bh * SEQ * DH;
    const float* vbase = g_v + (size_t)bh * SEQ * DH;
    const float* dbase = dist + ((size_t)b * SEQ + q0) * SEQ;

    const int frow = tid >> 5, fq = (tid & 31) * 4;   // Q/K/V fill coords
    const int drow = tid >> 4, dq = (tid & 15) * 4;   // D fill coords

#define FILL_K(kt) {                                                            \
        _Pragma("unroll")                                                       \
        for (int t = 0; t < 4; t++) {                                           \
            int key = frow + t * 16;                                            \
            cpa16(&Ks[key * 132 + fq],                                          \
                  &kbase[(size_t)((kt) * 64 + key) * DH + fq]);                 \
        }                                                                       \
        CP_COMMIT(); }
#define FILL_V(kt) {                                                            \
        _Pragma("unroll")                                                       \
        for (int t = 0; t < 4; t++) {                                           \
            int key = frow + t * 16;                                            \
            cpa16(&Vs[key * 136 + fq],                                          \
                  &vbase[(size_t)((kt) * 64 + key) * DH + fq]);                 \
        }                                                                       \
        CP_COMMIT(); }
#define FILL_D(kt) {                                                            \
        _Pragma("unroll")                                                       \
        for (int t = 0; t < 4; t++) {                                           \
            int row = drow + t * 32;                                            \
            cpa16(&Ds[row * 68 + dq],                                           \
                  &dbase[(size_t)row * SEQ + (kt) * 64 + dq]);                  \
        }                                                                       \
        CP_COMMIT(); }

    // prologue: [Q + K(0) + D(0)] group, then [V(0)] group
    {
#pragma unroll
        for (int t = 0; t < 8; t++) {
            int row = frow + t * 16;
            cpa16(&Qs[row * 132 + fq], &qbase[(size_t)(q0 + row) * DH + fq]);
        }
#pragma unroll
        for (int t = 0; t < 4; t++) {
            int key = frow + t * 16;
            cpa16(&Ks[key * 132 + fq], &kbase[(size_t)key * DH + fq]);
        }
#pragma unroll
        for (int t = 0; t < 4; t++) {
            int row = drow + t * 32;
            cpa16(&Ds[row * 68 + dq], &dbase[(size_t)row * SEQ + dq]);
        }
        CP_COMMIT();
        FILL_V(0);
        Msa[tid] = (mask[b * SEQ + tid] == 0.0f) ? -1e9f : 0.0f;
    }

    float O[8][4];
#pragma unroll
    for (int nf = 0; nf < 8; nf++)
#pragma unroll
        for (int i = 0; i < 4; i++) O[nf][i] = 0.0f;
    float l_t[2] = {0.0f, 0.0f};

    for (int kt = 0; kt < 8; kt++) {
        const int k0 = kt * 64;
        CP_WAIT(1);                       // K(kt)+D(kt) (and Q, Msa) ready
        __syncthreads();

        // S = Q @ K^T : this warp covers 16 rows x 32 keys (its wn half)
        float s[4][4];
#pragma unroll
        for (int nf = 0; nf < 4; nf++)
#pragma unroll
            for (int i = 0; i < 4; i++) s[nf][i] = 0.0f;
#pragma unroll
        for (int kb = 0; kb < 16; kb++) {
            const int k8 = kb * 8;
            unsigned a[4];
            a[0] = Qs[(m0 + g) * 132 + k8 + c];
            a[1] = Qs[(m0 + g + 8) * 132 + k8 + c];
            a[2] = Qs[(m0 + g) * 132 + k8 + c + 4];
            a[3] = Qs[(m0 + g + 8) * 132 + k8 + c + 4];
#pragma unroll
            for (int nf = 0; nf < 4; nf++) {
                unsigned bfr[2];
                int krow = (wn * 4 + nf) * 8 + g;
                bfr[0] = Ks[krow * 132 + k8 + c];
                bfr[1] = Ks[krow * 132 + k8 + c + 4];
                mma8(s[nf], a, bfr);
            }
        }
        __syncthreads();                  // Ks fully consumed
        if (kt < 7) FILL_K(kt + 1);       // overlaps softmax + PV

        // softmax (no max-tracking): p = exp(s + Ds + Msa); accumulate l
#pragma unroll
        for (int rr = 0; rr < 2; rr++) {
            const float* dsr = &Ds[(m0 + g + rr * 8) * 68 + wn * 32];
#pragma unroll
            for (int nf = 0; nf < 4; nf++) {
                int col = nf * 8 + 2 * c;            // within 32-key half
                int gcol = wn * 32 + col;            // within 64-key tile
                float2 dv = *(const float2*)&dsr[col];
                float s0 = s[nf][rr * 2 + 0] + dv.x + Msa[k0 + gcol];
                float s1 = s[nf][rr * 2 + 1] + dv.y + Msa[k0 + gcol + 1];
                float p0 = __expf(s0);
                float p1 = __expf(s1);
                l_t[rr] += p0 + p1;
                *(uint2*)&Ps[(m0 + g + rr * 8) * 68 + gcol] =
                    make_uint2(f2tf(p0), f2tf(p1));
            }
        }
        if (kt < 7) CP_WAIT(1); else CP_WAIT(0);   // V(kt) ready (K(kt+1) may pend)
        __syncthreads();                  // Ps complete + Vs ready + Ds consumed
        if (kt < 7) FILL_D(kt + 1);       // overlaps PV

        // O += P @ V : 16 rows x 64 D-cols (this wn half), k = 64
#pragma unroll
        for (int kb = 0; kb < 8; kb++) {
            const int k8 = kb * 8;
            unsigned a[4];
            a[0] = Ps[(m0 + g) * 68 + k8 + c];
            a[1] = Ps[(m0 + g + 8) * 68 + k8 + c];
            a[2] = Ps[(m0 + g) * 68 + k8 + c + 4];
            a[3] = Ps[(m0 + g + 8) * 68 + k8 + c + 4];
#pragma unroll
            for (int nf = 0; nf < 8; nf++) {
                int ncol = wn * 64 + nf * 8;
                unsigned bfr[2];
                bfr[0] = Vs[(k8 + c) * 136 + ncol + g];
                bfr[1] = Vs[(k8 + c + 4) * 136 + ncol + g];
                mma8(O[nf], a, bfr);
            }
        }
        __syncthreads();                  // Vs + Ps consumed
        if (kt < 7) FILL_V(kt + 1);       // overlaps next S-MMA
    }

    // final l reduction: quad lanes -> per-half partial -> cross-half sum
#pragma unroll
    for (int rr = 0; rr < 2; rr++) {
        float lv = l_t[rr];
        lv += __shfl_xor_sync(0xffffffffu, lv, 1);
        lv += __shfl_xor_sync(0xffffffffu, lv, 2);
        if (c == 0) Lp[wn * 128 + m0 + g + rr * 8] = lv;
    }
    __syncthreads();

#pragma unroll
    for (int rr = 0; rr < 2; rr++) {
        int row = m0 + g + rr * 8;
        float l = Lp[row] + Lp[128 + row];
        float inv = (l > 0.0f) ? 1.0f / l : 0.0f;
        float* orow = g_y1 + ((size_t)b * SEQ + q0 + row) * HD + h * DH + wn * 64;
#pragma unroll
        for (int nf = 0; nf < 8; nf++) {
            int col = nf * 8 + 2 * c;
            *(float2*)&orow[col] = make_float2(rtf(O[nf][rr * 2 + 0] * inv),
                                               rtf(O[nf][rr * 2 + 1] * inv));
        }
    }
}

// ---------------------------------------------------------------------------
// Output projection: out = (y1 @ Wo + bo) * mask
// grid NROWS/32 = 256, 256 thr (wm 0..1 x 16 rows, wn 0..3 x 32 cols)
// K staged 64 (16 stages), double-buffered: As[32][68] + Bs[64][136] per stage
// ---------------------------------------------------------------------------
#define OP_STG 10880
__global__ __launch_bounds__(256, 2) void oproj_kernel(
    const float* __restrict__ bo, const float* __restrict__ mask,
    float* __restrict__ out)
{
    extern __shared__ unsigned sm[];
    const int tid = threadIdx.x;
    const int wid = tid >> 5, lane = tid & 31;
    const int g = lane >> 2, c = lane & 3;
    const int wm = wid & 1, wn = wid >> 1;      // warp tile 16 x 32
    const int r0 = blockIdx.x * 32;
    const float* abase = g_y1 + (size_t)r0 * HD;

    const int arow = tid >> 4, aq = (tid & 15) * 4;  // A: 2 chunks/thread
    const int bkk = tid >> 5, bq_ = (tid & 31) * 4;  // B: 8 chunks/thread
#define OP_FILL(ks, buf) {                                                      \
        unsigned* As = sm + (buf) * OP_STG;                                     \
        unsigned* Bs = As + 2176;                                               \
        const int k0 = (ks) * 64;                                               \
        _Pragma("unroll")                                                       \
        for (int t = 0; t < 2; t++) {                                           \
            int row = arow + t * 16;                                            \
            cpa16(&As[row * 68 + aq], &abase[(size_t)row * HD + k0 + aq]);      \
        }                                                                       \
        _Pragma("unroll")                                                       \
        for (int t = 0; t < 8; t++) {                                           \
            int kk = bkk + t * 8;                                               \
            cpa16(&Bs[kk * 136 + bq_], &g_wo[(size_t)(k0 + kk) * DH + bq_]);    \
        }                                                                       \
        CP_COMMIT(); }

    float acc[4][4];
#pragma unroll
    for (int nf = 0; nf < 4; nf++)
#pragma unroll
        for (int i = 0; i < 4; i++) acc[nf][i] = 0.0f;

    OP_FILL(0, 0);
    for (int ks = 0; ks < 16; ks++) {
        if (ks < 15) { OP_FILL(ks + 1, (ks + 1) & 1); CP_WAIT(1); }
        else         { CP_WAIT(0); }
        __syncthreads();
        const unsigned* As = sm + (ks & 1) * OP_STG;
        const unsigned* Bs = As + 2176;
#pragma unroll
        for (int kb = 0; kb < 8; kb++) {
            const int k8 = kb * 8;
            unsigned a[4];
            int row = wm * 16;
            a[0] = As[(row + g) * 68 + k8 + c];
            a[1] = As[(row + g + 8) * 68 + k8 + c];
            a[2] = As[(row + g) * 68 + k8 + c + 4];
            a[3] = As[(row + g + 8) * 68 + k8 + c + 4];
#pragma unroll
            for (int nf = 0; nf < 4; nf++) {
                int col = wn * 32 + nf * 8;
                unsigned b[2];
                b[0] = Bs[(k8 + c) * 136 + col + g];
                b[1] = Bs[(k8 + c + 4) * 136 + col + g];
                mma8(acc[nf], a, b);
            }
        }
        __syncthreads();
    }

#pragma unroll
    for (int rr = 0; rr < 2; rr++) {
        int row = r0 + wm * 16 + g + rr * 8;
        float mm = mask[row];
#pragma unroll
        for (int nf = 0; nf < 4; nf++) {
            int col = wn * 32 + nf * 8 + 2 * c;
            float v0 = (acc[nf][rr * 2 + 0] + bo[col]) * mm;
            float v1 = (acc[nf][rr * 2 + 1] + bo[col + 1]) * mm;
            *(float2*)&out[(size_t)row * DH + col] = make_float2(v0, v1);
        }
    }
}

// ---------------------------------------------------------------------------
extern "C" void kernel_launch(void* const* d_in, const int* in_sizes, int n_in,
                              void* d_out, int out_size)
{
    const float* x    = (const float*)d_in[0];
    const float* dist = (const float*)d_in[1];
    const float* mask = (const float*)d_in[2];
    const float* Wq   = (const float*)d_in[3];
    const float* bq   = (const float*)d_in[4];
    const float* Wk   = (const float*)d_in[5];
    const float* bk   = (const float*)d_in[6];
    const float* Wv   = (const float*)d_in[7];
    const float* bv   = (const float*)d_in[8];
    const float* Wo   = (const float*)d_in[9];
    const float* bo   = (const float*)d_in[10];
    float* out = (float*)d_out;

    const int proj_smem = PROJ_STG * 2 * 4;                        // 71680
    const int attn_smem = (16896 + 8448 + 8704 + 8704 + 8704 + 512 + 256) * 4; // 208896
    const int op_smem   = OP_STG * 2 * 4;                          // 87040
    static int configured = 0;
    if (!configured) {
        cudaFuncSetAttribute(proj_kernel, cudaFuncAttributeMaxDynamicSharedMemorySize, proj_smem);
        cudaFuncSetAttribute(attn_kernel, cudaFuncAttributeMaxDynamicSharedMemorySize, attn_smem);
        cudaFuncSetAttribute(oproj_kernel, cudaFuncAttributeMaxDynamicSharedMemorySize, op_smem);
        configured = 1;
    }

    prep_kernel<<<1024, 256>>>(x, Wq, Wk, Wv, Wo);
    proj_kernel<<<dim3(HD/128, NROWS/128, 3), 256, proj_smem>>>(mask, bq, bk, bv);
    attn_kernel<<<dim3(SEQ/128, BB*NH), 512, attn_smem>>>(dist, mask);
    oproj_kernel<<<dim3(NROWS/32), 256, op_smem>>>(bo, mask, out);
}

// round 8
// speedup vs baseline: 2.0372x; 1.2743x over previous
#include <cuda_runtime.h>
#include <cuda_fp16.h>

#define BB   16
#define SEQ  512
#define NH   8
#define DH   128
#define HD   1024
#define NROWS (BB*SEQ)            // 8192
#define SCALE 0.08838834764831843f

// Scratch (no device allocation allowed)
__device__ __half g_q [BB*NH*SEQ*DH];  // [B,H,N,D] masked*scaled fp16
__device__ __half g_k [BB*NH*SEQ*DH];  // [B,H,N,D] masked fp16
__device__ __half g_v [BB*NH*SEQ*DH];  // [B,H,N,D] masked fp16
__device__ __half g_dh[BB*SEQ*SEQ];    // dist + key-mask(-1e9), fp16
__device__ float  g_y1[NROWS*HD];      // [B,N,H*D] attn out, tf32-rounded
__device__ float  g_xr[NROWS*DH];      // x rounded
__device__ float  g_wq[DH*HD], g_wk[DH*HD], g_wv[DH*HD], g_wo[HD*DH];

__device__ __forceinline__ unsigned f2tf(float f) {
    unsigned u;
    asm("cvt.rna.tf32.f32 %0, %1;" : "=r"(u) : "f"(f));
    return u;
}
__device__ __forceinline__ float rtf(float f) { return __uint_as_float(f2tf(f)); }

__device__ __forceinline__ void cpa16(void* dst_smem, const void* src_gmem) {
    unsigned s = (unsigned)__cvta_generic_to_shared(dst_smem);
    asm volatile("cp.async.cg.shared.global [%0], [%1], 16;\n" :: "r"(s), "l"(src_gmem));
}
#define CP_COMMIT() asm volatile("cp.async.commit_group;\n")
#define CP_WAIT(n)  asm volatile("cp.async.wait_group %0;\n" :: "n"(n))

__device__ __forceinline__ unsigned smaddr(const void* p) {
    return (unsigned)__cvta_generic_to_shared(p);
}
// tf32 k8 mma (proj/oproj)
__device__ __forceinline__ void mma8(float* d, const unsigned* a, const unsigned* b) {
    asm volatile(
        "mma.sync.aligned.m16n8k8.row.col.f32.tf32.tf32.f32 "
        "{%0,%1,%2,%3}, {%4,%5,%6,%7}, {%8,%9}, {%0,%1,%2,%3};"
        : "+f"(d[0]), "+f"(d[1]), "+f"(d[2]), "+f"(d[3])
        : "r"(a[0]), "r"(a[1]), "r"(a[2]), "r"(a[3]), "r"(b[0]), "r"(b[1]));
}
// fp16 k16 mma (attention)
__device__ __forceinline__ void mma16(float* d, const unsigned* a, const unsigned* b) {
    asm volatile(
        "mma.sync.aligned.m16n8k16.row.col.f32.f16.f16.f32 "
        "{%0,%1,%2,%3}, {%4,%5,%6,%7}, {%8,%9}, {%0,%1,%2,%3};"
        : "+f"(d[0]), "+f"(d[1]), "+f"(d[2]), "+f"(d[3])
        : "r"(a[0]), "r"(a[1]), "r"(a[2]), "r"(a[3]), "r"(b[0]), "r"(b[1]));
}
// ldmatrix x4 transposed (V^T fragments)
__device__ __forceinline__ void ldsm4t(unsigned* r, unsigned a) {
    asm volatile("ldmatrix.sync.aligned.m8n8.x4.trans.shared.b16 {%0,%1,%2,%3}, [%4];"
        : "=r"(r[0]), "=r"(r[1]), "=r"(r[2]), "=r"(r[3]) : "r"(a));
}

// ---------------------------------------------------------------------------
// prep: round x + weights to tf32. grid 1024 x 256
// ---------------------------------------------------------------------------
__global__ void prep_kernel(const float* __restrict__ x,
                            const float* __restrict__ Wq, const float* __restrict__ Wk,
                            const float* __restrict__ Wv, const float* __restrict__ Wo)
{
    int i = blockIdx.x * 256 + threadIdx.x;       // float4 index
    if (i < NROWS*DH/4) {
        float4 v = ((const float4*)x)[i];
        ((float4*)g_xr)[i] = make_float4(rtf(v.x), rtf(v.y), rtf(v.z), rtf(v.w));
    }
    if (i < DH*HD/4) {
        float4 a = ((const float4*)Wq)[i];
        ((float4*)g_wq)[i] = make_float4(rtf(a.x), rtf(a.y), rtf(a.z), rtf(a.w));
        float4 b = ((const float4*)Wk)[i];
        ((float4*)g_wk)[i] = make_float4(rtf(b.x), rtf(b.y), rtf(b.z), rtf(b.w));
        float4 c = ((const float4*)Wv)[i];
        ((float4*)g_wv)[i] = make_float4(rtf(c.x), rtf(c.y), rtf(c.z), rtf(c.w));
        float4 d = ((const float4*)Wo)[i];
        ((float4*)g_wo)[i] = make_float4(rtf(d.x), rtf(d.y), rtf(d.z), rtf(d.w));
    }
}

// ---------------------------------------------------------------------------
// dprep: g_dh = fp16(dist + (mask[key]? 0 : -1e9)). grid 4096 x 256
// ---------------------------------------------------------------------------
__global__ void dprep_kernel(const float* __restrict__ dist,
                             const float* __restrict__ mask)
{
    size_t i4 = (size_t)blockIdx.x * 256 + threadIdx.x;   // float4 idx, 1048576 total
    float4 v = ((const float4*)dist)[i4];
    int m = (int)(i4 & 127) * 4;           // key index (last dim)
    int b = (int)(i4 >> 16);               // batch
    const float* mrow = mask + b * SEQ;
    float a0 = v.x + ((mrow[m + 0] == 0.0f) ? -1e9f : 0.0f);
    float a1 = v.y + ((mrow[m + 1] == 0.0f) ? -1e9f : 0.0f);
    float a2 = v.z + ((mrow[m + 2] == 0.0f) ? -1e9f : 0.0f);
    float a3 = v.w + ((mrow[m + 3] == 0.0f) ? -1e9f : 0.0f);
    ((__half2*)g_dh)[i4 * 2 + 0] = __floats2half2_rn(a0, a1);
    ((__half2*)g_dh)[i4 * 2 + 1] = __floats2half2_rn(a2, a3);
}

// ---------------------------------------------------------------------------
// QKV projection (tf32): out = (x @ W + b) * mask (* scale for q) -> fp16 [B,H,N,D]
// grid (HD/128, NROWS/128, 3), 256 thr; tile 128x128, K staged 32, double-buf
// ---------------------------------------------------------------------------
#define PROJ_STG 8960
__global__ __launch_bounds__(256, 2) void proj_kernel(
    const float* __restrict__ mask,
    const float* __restrict__ bq, const float* __restrict__ bk,
    const float* __restrict__ bv)
{
    extern __shared__ unsigned sm[];
    const int tid = threadIdx.x;
    const int wid = tid >> 5, lane = tid & 31;
    const int g = lane >> 2, c = lane & 3;
    const int wm = wid & 3, wn = wid >> 2;       // warp tile 32 x 64
    const int c0 = blockIdx.x * 128;
    const int r0 = blockIdx.y * 128;
    const int sel = blockIdx.z;
    const float* W    = (sel == 0) ? g_wq : (sel == 1) ? g_wk : g_wv;
    const float* bias = (sel == 0) ? bq : (sel == 1) ? bk : bv;
    __half*      out  = (sel == 0) ? g_q : (sel == 1) ? g_k : g_v;
    const float extra = (sel == 0) ? SCALE : 1.0f;
    const float* xbase = g_xr + (size_t)r0 * DH;

    const int arow = tid >> 3, aq = (tid & 7) * 4;
    const int bkk = tid >> 5, bq_ = (tid & 31) * 4;
#define PROJ_FILL(ks, buf) {                                                   \
        unsigned* As = sm + (buf) * PROJ_STG;                                  \
        unsigned* Bs = As + 4608;                                              \
        const int k0 = (ks) * 32;                                              \
        _Pragma("unroll")                                                      \
        for (int t = 0; t < 4; t++) {                                          \
            int row = arow + t * 32;                                           \
            cpa16(&As[row * 36 + aq], &xbase[(size_t)row * DH + k0 + aq]);     \
        }                                                                      \
        _Pragma("unroll")                                                      \
        for (int t = 0; t < 4; t++) {                                          \
            int kk = bkk + t * 8;                                              \
            cpa16(&Bs[kk * 136 + bq_], &W[(size_t)(k0 + kk) * HD + c0 + bq_]); \
        }                                                                      \
        CP_COMMIT(); }

    float acc[2][8][4];
#pragma unroll
    for (int mf = 0; mf < 2; mf++)
#pragma unroll
        for (int nf = 0; nf < 8; nf++)
#pragma unroll
            for (int i = 0; i < 4; i++) acc[mf][nf][i] = 0.0f;

    PROJ_FILL(0, 0);
    for (int ks = 0; ks < 4; ks++) {
        if (ks < 3) { PROJ_FILL(ks + 1, (ks + 1) & 1); CP_WAIT(1); }
        else        { CP_WAIT(0); }
        __syncthreads();
        const unsigned* As = sm + (ks & 1) * PROJ_STG;
        const unsigned* Bs = As + 4608;
#pragma unroll
        for (int kb = 0; kb < 4; kb++) {
            const int k8 = kb * 8;
            unsigned a[2][4];
#pragma unroll
            for (int mf = 0; mf < 2; mf++) {
                int row = wm * 32 + mf * 16;
                a[mf][0] = As[(row + g) * 36 + k8 + c];
                a[mf][1] = As[(row + g + 8) * 36 + k8 + c];
                a[mf][2] = As[(row + g) * 36 + k8 + c + 4];
                a[mf][3] = As[(row + g + 8) * 36 + k8 + c + 4];
            }
#pragma unroll
            for (int nf = 0; nf < 8; nf++) {
                int col = wn * 64 + nf * 8;
                unsigned b[2];
                b[0] = Bs[(k8 + c) * 136 + col + g];
                b[1] = Bs[(k8 + c + 4) * 136 + col + g];
                mma8(acc[0][nf], a[0], b);
                mma8(acc[1][nf], a[1], b);
            }
        }
        __syncthreads();
    }

#pragma unroll
    for (int mf = 0; mf < 2; mf++) {
#pragma unroll
        for (int rr = 0; rr < 2; rr++) {
            int row = r0 + wm * 32 + mf * 16 + g + rr * 8;
            int bI = row >> 9, n = row & 511;
            float mm = mask[row] * extra;
#pragma unroll
            for (int nf = 0; nf < 8; nf++) {
                int col = c0 + wn * 64 + nf * 8 + 2 * c;
                int h = col >> 7, d = col & 127;
                float v0 = (acc[mf][nf][rr * 2 + 0] + bias[col]) * mm;
                float v1 = (acc[mf][nf][rr * 2 + 1] + bias[col + 1]) * mm;
                *(__half2*)&out[(((size_t)bI * NH + h) * SEQ + n) * DH + d] =
                    __floats2half2_rn(v0, v1);
            }
        }
    }
}

// ---------------------------------------------------------------------------
// Flash attention fp16 (f32 accum), no-max softmax, dist+mask pre-fused fp16.
// grid (SEQ/128, BB*NH), 1024 thr: 32 warps = 8 row-groups x 4 quarters.
// smem (halves): Qs[128][136] Ks[64][136] Vs[64][136] Ps[128][72] Ds[128][72]
//                + float Lp[512]   => 108544 B
// ---------------------------------------------------------------------------
#define QSTR 136
#define PSTR 72
__global__ __launch_bounds__(1024, 1) void attn_kernel()
{
    extern __shared__ __half smh[];
    __half* Qs = smh;                    // 17408 h
    __half* Ks = Qs + 128 * QSTR;        //  8704 h
    __half* Vs = Ks + 64 * QSTR;         //  8704 h
    __half* Ps = Vs + 64 * QSTR;         //  9216 h
    __half* Ds = Ps + 128 * PSTR;        //  9216 h
    float*  Lp = (float*)(Ds + 128 * PSTR);  // 512 f

    const int tid = threadIdx.x;
    const int wid = tid >> 5, lane = tid & 31;
    const int g = lane >> 2, c = lane & 3;
    const int wm = wid & 7, wn = wid >> 3;   // 8 row-groups x 4 quarters
    const int bh = blockIdx.y;
    const int b = bh >> 3, h = bh & 7;
    const int q0 = blockIdx.x * 128;
    const int m0 = wm * 16;

    const __half* qbase = g_q + (size_t)bh * SEQ * DH;
    const __half* kbase = g_k + (size_t)bh * SEQ * DH;
    const __half* vbase = g_v + (size_t)bh * SEQ * DH;
    const __half* dbase = g_dh + ((size_t)b * SEQ + q0) * SEQ;

    const int frow = tid >> 4, fc8 = (tid & 15) * 8;   // K/V: 64 rows x 16 chunks
    const int drow = tid >> 3, dc8 = (tid & 7) * 8;    // D: 128 rows x 8 chunks

#define FILL_K(kt) {                                                            \
        cpa16(&Ks[frow * QSTR + fc8],                                           \
              &kbase[(size_t)((kt) * 64 + frow) * DH + fc8]);                   \
        CP_COMMIT(); }
#define FILL_V(kt) {                                                            \
        cpa16(&Vs[frow * QSTR + fc8],                                           \
              &vbase[(size_t)((kt) * 64 + frow) * DH + fc8]);                   \
        CP_COMMIT(); }
#define FILL_D(kt) {                                                            \
        cpa16(&Ds[drow * PSTR + dc8],                                           \
              &dbase[(size_t)drow * SEQ + (kt) * 64 + dc8]);                    \
        CP_COMMIT(); }

    // prologue: [Q + K(0) + D(0)] group, then [V(0)] group
    {
#pragma unroll
        for (int t = 0; t < 2; t++) {
            int i = tid + t * 1024;
            int row = i >> 4, c8 = (i & 15) * 8;
            cpa16(&Qs[row * QSTR + c8], &qbase[(size_t)(q0 + row) * DH + c8]);
        }
        cpa16(&Ks[frow * QSTR + fc8], &kbase[(size_t)frow * DH + fc8]);
        cpa16(&Ds[drow * PSTR + dc8], &dbase[(size_t)drow * SEQ + dc8]);
        CP_COMMIT();
        FILL_V(0);
    }

    float O[4][4];
#pragma unroll
    for (int nf = 0; nf < 4; nf++)
#pragma unroll
        for (int i = 0; i < 4; i++) O[nf][i] = 0.0f;
    float l_t[2] = {0.0f, 0.0f};

    for (int kt = 0; kt < 8; kt++) {
        CP_WAIT(1);                       // K(kt)+D(kt) ready
        __syncthreads();

        // S = Q @ K^T : 16 rows x 16 keys (this warp's quarter)
        float s[2][4];
#pragma unroll
        for (int nf = 0; nf < 2; nf++)
#pragma unroll
            for (int i = 0; i < 4; i++) s[nf][i] = 0.0f;
#pragma unroll
        for (int kb = 0; kb < 8; kb++) {
            const int k16 = kb * 16 + 2 * c;
            unsigned a[4];
            a[0] = *(const unsigned*)&Qs[(m0 + g) * QSTR + k16];
            a[1] = *(const unsigned*)&Qs[(m0 + g + 8) * QSTR + k16];
            a[2] = *(const unsigned*)&Qs[(m0 + g) * QSTR + k16 + 8];
            a[3] = *(const unsigned*)&Qs[(m0 + g + 8) * QSTR + k16 + 8];
#pragma unroll
            for (int nf = 0; nf < 2; nf++) {
                int col = wn * 16 + nf * 8 + g;
                unsigned bfr[2];
                bfr[0] = *(const unsigned*)&Ks[col * QSTR + k16];
                bfr[1] = *(const unsigned*)&Ks[col * QSTR + k16 + 8];
                mma16(s[nf], a, bfr);
            }
        }
        __syncthreads();                  // Ks fully consumed
        if (kt < 7) FILL_K(kt + 1);

        // softmax: p = exp(s + Ds)  (Ds already has dist + key-mask)
#pragma unroll
        for (int rr = 0; rr < 2; rr++) {
            const int row = m0 + g + rr * 8;
#pragma unroll
            for (int nf = 0; nf < 2; nf++) {
                int gcol = wn * 16 + nf * 8 + 2 * c;
                float2 dv = __half22float2(*(const __half2*)&Ds[row * PSTR + gcol]);
                float p0 = __expf(s[nf][rr * 2 + 0] + dv.x);
                float p1 = __expf(s[nf][rr * 2 + 1] + dv.y);
                l_t[rr] += p0 + p1;
                *(__half2*)&Ps[row * PSTR + gcol] = __floats2half2_rn(p0, p1);
            }
        }
        if (kt < 7) CP_WAIT(1); else CP_WAIT(0);   // V(kt) ready
        __syncthreads();                  // Ps complete + Vs ready + Ds consumed
        if (kt < 7) FILL_D(kt + 1);

        // O += P @ V : 16 rows x 32 D-cols (this warp's quarter), k = 64
#pragma unroll
        for (int ks = 0; ks < 4; ks++) {
            const int k16 = ks * 16;
            unsigned a[4];
            a[0] = *(const unsigned*)&Ps[(m0 + g) * PSTR + k16 + 2 * c];
            a[1] = *(const unsigned*)&Ps[(m0 + g + 8) * PSTR + k16 + 2 * c];
            a[2] = *(const unsigned*)&Ps[(m0 + g) * PSTR + k16 + 2 * c + 8];
            a[3] = *(const unsigned*)&Ps[(m0 + g + 8) * PSTR + k16 + 2 * c + 8];
#pragma unroll
            for (int nb = 0; nb < 2; nb++) {
                unsigned v[4];
                unsigned vaddr = smaddr(&Vs[(k16 + (lane & 15)) * QSTR +
                                            wn * 32 + nb * 16 + ((lane >> 4) << 3)]);
                ldsm4t(v, vaddr);
                mma16(O[nb * 2 + 0], a, v);
                mma16(O[nb * 2 + 1], a, v + 2);
            }
        }
        __syncthreads();                  // Vs + Ps consumed
        if (kt < 7) FILL_V(kt + 1);
    }

    // l: reduce over quad lanes, then over 4 quarters via smem
#pragma unroll
    for (int rr = 0; rr < 2; rr++) {
        float lv = l_t[rr];
        lv += __shfl_xor_sync(0xffffffffu, lv, 1);
        lv += __shfl_xor_sync(0xffffffffu, lv, 2);
        if (c == 0) Lp[wn * 128 + m0 + g + rr * 8] = lv;
    }
    __syncthreads();

#pragma unroll
    for (int rr = 0; rr < 2; rr++) {
        int row = m0 + g + rr * 8;
        float l = Lp[row] + Lp[128 + row] + Lp[256 + row] + Lp[384 + row];
        float inv = (l > 0.0f) ? 1.0f / l : 0.0f;
        float* orow = g_y1 + ((size_t)b * SEQ + q0 + row) * HD + h * DH + wn * 32;
#pragma unroll
        for (int nf = 0; nf < 4; nf++) {
            int col = nf * 8 + 2 * c;
            *(float2*)&orow[col] = make_float2(rtf(O[nf][rr * 2 + 0] * inv),
                                               rtf(O[nf][rr * 2 + 1] * inv));
        }
    }
}

// ---------------------------------------------------------------------------
// Output projection (tf32): out = (y1 @ Wo + bo) * mask
// grid NROWS/32 = 256, 256 thr; K staged 64, double-buffered
// ---------------------------------------------------------------------------
#define OP_STG 10880
__global__ __launch_bounds__(256, 2) void oproj_kernel(
    const float* __restrict__ bo, const float* __restrict__ mask,
    float* __restrict__ out)
{
    extern __shared__ unsigned sm[];
    const int tid = threadIdx.x;
    const int wid = tid >> 5, lane = tid & 31;
    const int g = lane >> 2, c = lane & 3;
    const int wm = wid & 1, wn = wid >> 1;      // warp tile 16 x 32
    const int r0 = blockIdx.x * 32;
    const float* abase = g_y1 + (size_t)r0 * HD;

    const int arow = tid >> 4, aq = (tid & 15) * 4;
    const int bkk = tid >> 5, bq_ = (tid & 31) * 4;
#define OP_FILL(ks, buf) {                                                      \
        unsigned* As = sm + (buf) * OP_STG;                                     \
        unsigned* Bs = As + 2176;                                               \
        const int k0 = (ks) * 64;                                               \
        _Pragma("unroll")                                                       \
        for (int t = 0; t < 2; t++) {                                           \
            int row = arow + t * 16;                                            \
            cpa16(&As[row * 68 + aq], &abase[(size_t)row * HD + k0 + aq]);      \
        }                                                                       \
        _Pragma("unroll")                                                       \
        for (int t = 0; t < 8; t++) {                                           \
            int kk = bkk + t * 8;                                               \
            cpa16(&Bs[kk * 136 + bq_], &g_wo[(size_t)(k0 + kk) * DH + bq_]);    \
        }                                                                       \
        CP_COMMIT(); }

    float acc[4][4];
#pragma unroll
    for (int nf = 0; nf < 4; nf++)
#pragma unroll
        for (int i = 0; i < 4; i++) acc[nf][i] = 0.0f;

    OP_FILL(0, 0);
    for (int ks = 0; ks < 16; ks++) {
        if (ks < 15) { OP_FILL(ks + 1, (ks + 1) & 1); CP_WAIT(1); }
        else         { CP_WAIT(0); }
        __syncthreads();
        const unsigned* As = sm + (ks & 1) * OP_STG;
        const unsigned* Bs = As + 2176;
#pragma unroll
        for (int kb = 0; kb < 8; kb++) {
            const int k8 = kb * 8;
            unsigned a[4];
            int row = wm * 16;
            a[0] = As[(row + g) * 68 + k8 + c];
            a[1] = As[(row + g + 8) * 68 + k8 + c];
            a[2] = As[(row + g) * 68 + k8 + c + 4];
            a[3] = As[(row + g + 8) * 68 + k8 + c + 4];
#pragma unroll
            for (int nf = 0; nf < 4; nf++) {
                int col = wn * 32 + nf * 8;
                unsigned b[2];
                b[0] = Bs[(k8 + c) * 136 + col + g];
                b[1] = Bs[(k8 + c + 4) * 136 + col + g];
                mma8(acc[nf], a, b);
            }
        }
        __syncthreads();
    }

#pragma unroll
    for (int rr = 0; rr < 2; rr++) {
        int row = r0 + wm * 16 + g + rr * 8;
        float mm = mask[row];
#pragma unroll
        for (int nf = 0; nf < 4; nf++) {
            int col = wn * 32 + nf * 8 + 2 * c;
            float v0 = (acc[nf][rr * 2 + 0] + bo[col]) * mm;
            float v1 = (acc[nf][rr * 2 + 1] + bo[col + 1]) * mm;
            *(float2*)&out[(size_t)row * DH + col] = make_float2(v0, v1);
        }
    }
}

// ---------------------------------------------------------------------------
extern "C" void kernel_launch(void* const* d_in, const int* in_sizes, int n_in,
                              void* d_out, int out_size)
{
    const float* x    = (const float*)d_in[0];
    const float* dist = (const float*)d_in[1];
    const float* mask = (const float*)d_in[2];
    const float* Wq   = (const float*)d_in[3];
    const float* bq   = (const float*)d_in[4];
    const float* Wk   = (const float*)d_in[5];
    const float* bk   = (const float*)d_in[6];
    const float* Wv   = (const float*)d_in[7];
    const float* bv   = (const float*)d_in[8];
    const float* Wo   = (const float*)d_in[9];
    const float* bo   = (const float*)d_in[10];
    float* out = (float*)d_out;

    const int proj_smem = PROJ_STG * 2 * 4;                        // 71680
    const int attn_smem = (17408 + 8704 + 8704 + 9216 + 9216) * 2 + 512 * 4; // 108544
    const int op_smem   = OP_STG * 2 * 4;                          // 87040
    static int configured = 0;
    if (!configured) {
        cudaFuncSetAttribute(proj_kernel, cudaFuncAttributeMaxDynamicSharedMemorySize, proj_smem);
        cudaFuncSetAttribute(attn_kernel, cudaFuncAttributeMaxDynamicSharedMemorySize, attn_smem);
        cudaFuncSetAttribute(oproj_kernel, cudaFuncAttributeMaxDynamicSharedMemorySize, op_smem);
        configured = 1;
    }

    prep_kernel<<<1024, 256>>>(x, Wq, Wk, Wv, Wo);
    dprep_kernel<<<4096, 256>>>(dist, mask);
    proj_kernel<<<dim3(HD/128, NROWS/128, 3), 256, proj_smem>>>(mask, bq, bk, bv);
    attn_kernel<<<dim3(SEQ/128, BB*NH), 1024, attn_smem>>>();
    oproj_kernel<<<dim3(NROWS/32), 256, op_smem>>>(bo, mask, out);
}

// round 9
// speedup vs baseline: 2.3885x; 1.1724x over previous
#include <cuda_runtime.h>
#include <cuda_fp16.h>

#define BB   16
#define SEQ  512
#define NH   8
#define DH   128
#define HD   1024
#define NROWS (BB*SEQ)            // 8192
#define SCALE 0.08838834764831843f

// Scratch (no device allocation allowed)
__device__ __half g_q  [BB*NH*SEQ*DH]; // [B,H,N,D] masked*scaled fp16
__device__ __half g_k  [BB*NH*SEQ*DH]; // [B,H,N,D] masked fp16
__device__ __half g_v  [BB*NH*SEQ*DH]; // [B,H,N,D] masked fp16
__device__ __half g_dh [BB*SEQ*SEQ];   // dist + key-mask(-inf), fp16
__device__ __half g_y1h[NROWS*HD];     // [B,N,H*D] attn out fp16
__device__ __half g_xh [NROWS*DH];     // x fp16
__device__ __half g_wqt[HD*DH];        // Wq^T [n][k] fp16
__device__ __half g_wkt[HD*DH];
__device__ __half g_wvt[HD*DH];
__device__ __half g_wot[DH*HD];        // Wo^T [n=128][k=1024] fp16

__device__ __forceinline__ void cpa16(void* dst_smem, const void* src_gmem) {
    unsigned s = (unsigned)__cvta_generic_to_shared(dst_smem);
    asm volatile("cp.async.cg.shared.global [%0], [%1], 16;\n" :: "r"(s), "l"(src_gmem));
}
#define CP_COMMIT() asm volatile("cp.async.commit_group;\n")
#define CP_WAIT(n)  asm volatile("cp.async.wait_group %0;\n" :: "n"(n))

// fp16 k16 mma, fp32 accum
__device__ __forceinline__ void mma16(float* d, const unsigned* a, const unsigned* b) {
    asm volatile(
        "mma.sync.aligned.m16n8k16.row.col.f32.f16.f16.f32 "
        "{%0,%1,%2,%3}, {%4,%5,%6,%7}, {%8,%9}, {%0,%1,%2,%3};"
        : "+f"(d[0]), "+f"(d[1]), "+f"(d[2]), "+f"(d[3])
        : "r"(a[0]), "r"(a[1]), "r"(a[2]), "r"(a[3]), "r"(b[0]), "r"(b[1]));
}
__device__ __forceinline__ unsigned smaddr(const void* p) {
    return (unsigned)__cvta_generic_to_shared(p);
}
__device__ __forceinline__ void ldsm4t(unsigned* r, unsigned a) {
    asm volatile("ldmatrix.sync.aligned.m8n8.x4.trans.shared.b16 {%0,%1,%2,%3}, [%4];"
        : "=r"(r[0]), "=r"(r[1]), "=r"(r[2]), "=r"(r[3]) : "r"(a));
}

// ---------------------------------------------------------------------------
// prep: x -> fp16. grid 1024 x 256
// ---------------------------------------------------------------------------
__global__ void prep_kernel(const float* __restrict__ x)
{
    int i = blockIdx.x * 256 + threadIdx.x;       // float4 index
    if (i < NROWS*DH/4) {
        float4 v = ((const float4*)x)[i];
        ((__half2*)g_xh)[i * 2 + 0] = __floats2half2_rn(v.x, v.y);
        ((__half2*)g_xh)[i * 2 + 1] = __floats2half2_rn(v.z, v.w);
    }
}

// ---------------------------------------------------------------------------
// weight transpose -> fp16: W[R=k][C=n] f32 -> Wt[C][R] h16. grid (32,32,4)
// ---------------------------------------------------------------------------
__global__ void wtrans_kernel(const float* __restrict__ Wq, const float* __restrict__ Wk,
                              const float* __restrict__ Wv, const float* __restrict__ Wo)
{
    __shared__ float t[32][33];
    const int z = blockIdx.z;
    const float* src = (z == 0) ? Wq : (z == 1) ? Wk : (z == 2) ? Wv : Wo;
    __half* dst = (z == 0) ? g_wqt : (z == 1) ? g_wkt : (z == 2) ? g_wvt : g_wot;
    const int R = (z < 3) ? DH : HD;
    const int C = (z < 3) ? HD : DH;
    if ((int)blockIdx.x * 32 >= C || (int)blockIdx.y * 32 >= R) return;
    const int tx = threadIdx.x, ty = threadIdx.y;
    const int r = blockIdx.y * 32, c = blockIdx.x * 32;
#pragma unroll
    for (int j = 0; j < 4; j++)
        t[ty + j*8][tx] = src[(size_t)(r + ty + j*8) * C + c + tx];
    __syncthreads();
#pragma unroll
    for (int j = 0; j < 4; j++)
        dst[(size_t)(c + ty + j*8) * R + r + tx] = __float2half_rn(t[tx][ty + j*8]);
}

// ---------------------------------------------------------------------------
// dprep: g_dh = fp16(dist + (mask[key]? 0 : -1e9)). grid 4096 x 256
// ---------------------------------------------------------------------------
__global__ void dprep_kernel(const float* __restrict__ dist,
                             const float* __restrict__ mask)
{
    size_t i4 = (size_t)blockIdx.x * 256 + threadIdx.x;
    float4 v = ((const float4*)dist)[i4];
    int m = (int)(i4 & 127) * 4;
    int b = (int)(i4 >> 16);
    const float* mrow = mask + b * SEQ;
    float a0 = v.x + ((mrow[m + 0] == 0.0f) ? -1e9f : 0.0f);
    float a1 = v.y + ((mrow[m + 1] == 0.0f) ? -1e9f : 0.0f);
    float a2 = v.z + ((mrow[m + 2] == 0.0f) ? -1e9f : 0.0f);
    float a3 = v.w + ((mrow[m + 3] == 0.0f) ? -1e9f : 0.0f);
    ((__half2*)g_dh)[i4 * 2 + 0] = __floats2half2_rn(a0, a1);
    ((__half2*)g_dh)[i4 * 2 + 1] = __floats2half2_rn(a2, a3);
}

// ---------------------------------------------------------------------------
// QKV projection fp16: out = (x @ W + b) * mask (* scale for q) -> fp16 [B,H,N,D]
// grid (HD/128, NROWS/128, 3), 256 thr; tile 128x128, K staged 64, double-buf
// smem/stage (halves): As[128][72] + Bs(Wt)[128][72] = 18432 h
// ---------------------------------------------------------------------------
#define PROJ_STG 18432
__global__ __launch_bounds__(256, 2) void proj_kernel(
    const float* __restrict__ mask,
    const float* __restrict__ bq, const float* __restrict__ bk,
    const float* __restrict__ bv)
{
    extern __shared__ __half smh[];
    const int tid = threadIdx.x;
    const int wid = tid >> 5, lane = tid & 31;
    const int g = lane >> 2, c = lane & 3;
    const int wm = wid & 3, wn = wid >> 2;       // warp tile 32 x 64
    const int c0 = blockIdx.x * 128;
    const int r0 = blockIdx.y * 128;
    const int sel = blockIdx.z;
    const __half* Wt  = (sel == 0) ? g_wqt : (sel == 1) ? g_wkt : g_wvt;
    const float* bias = (sel == 0) ? bq : (sel == 1) ? bk : bv;
    __half*      out  = (sel == 0) ? g_q : (sel == 1) ? g_k : g_v;
    const float extra = (sel == 0) ? SCALE : 1.0f;
    const __half* xbase = g_xh + (size_t)r0 * DH;
    const __half* wbase = Wt + (size_t)c0 * DH;

    const int frow = tid >> 3, fc8 = (tid & 7) * 8;   // 128 rows x 8 chunks
#define PROJ_FILL(ks, buf) {                                                    \
        __half* As = smh + (buf) * PROJ_STG;                                    \
        __half* Bs = As + 9216;                                                 \
        const int k0 = (ks) * 64;                                               \
        _Pragma("unroll")                                                       \
        for (int t = 0; t < 4; t++) {                                           \
            int row = frow + t * 32;                                            \
            cpa16(&As[row * 72 + fc8], &xbase[(size_t)row * DH + k0 + fc8]);    \
            cpa16(&Bs[row * 72 + fc8], &wbase[(size_t)row * DH + k0 + fc8]);    \
        }                                                                       \
        CP_COMMIT(); }

    float acc[2][8][4];
#pragma unroll
    for (int mf = 0; mf < 2; mf++)
#pragma unroll
        for (int nf = 0; nf < 8; nf++)
#pragma unroll
            for (int i = 0; i < 4; i++) acc[mf][nf][i] = 0.0f;

    PROJ_FILL(0, 0);
    for (int ks = 0; ks < 2; ks++) {
        if (ks < 1) { PROJ_FILL(1, 1); CP_WAIT(1); }
        else        { CP_WAIT(0); }
        __syncthreads();
        const __half* As = smh + (ks & 1) * PROJ_STG;
        const __half* Bs = As + 9216;
#pragma unroll
        for (int kb = 0; kb < 4; kb++) {
            const int k16 = kb * 16 + 2 * c;
            unsigned a[2][4];
#pragma unroll
            for (int mf = 0; mf < 2; mf++) {
                int row = wm * 32 + mf * 16;
                a[mf][0] = *(const unsigned*)&As[(row + g) * 72 + k16];
                a[mf][1] = *(const unsigned*)&As[(row + g + 8) * 72 + k16];
                a[mf][2] = *(const unsigned*)&As[(row + g) * 72 + k16 + 8];
                a[mf][3] = *(const unsigned*)&As[(row + g + 8) * 72 + k16 + 8];
            }
#pragma unroll
            for (int nf = 0; nf < 8; nf++) {
                int col = wn * 64 + nf * 8;
                unsigned b[2];
                b[0] = *(const unsigned*)&Bs[(col + g) * 72 + k16];
                b[1] = *(const unsigned*)&Bs[(col + g) * 72 + k16 + 8];
                mma16(acc[0][nf], a[0], b);
                mma16(acc[1][nf], a[1], b);
            }
        }
        __syncthreads();
    }

#pragma unroll
    for (int mf = 0; mf < 2; mf++) {
#pragma unroll
        for (int rr = 0; rr < 2; rr++) {
            int row = r0 + wm * 32 + mf * 16 + g + rr * 8;
            int bI = row >> 9, n = row & 511;
            float mm = mask[row] * extra;
#pragma unroll
            for (int nf = 0; nf < 8; nf++) {
                int col = c0 + wn * 64 + nf * 8 + 2 * c;
                int h = col >> 7, d = col & 127;
                float v0 = (acc[mf][nf][rr * 2 + 0] + bias[col]) * mm;
                float v1 = (acc[mf][nf][rr * 2 + 1] + bias[col + 1]) * mm;
                *(__half2*)&out[(((size_t)bI * NH + h) * SEQ + n) * DH + d] =
                    __floats2half2_rn(v0, v1);
            }
        }
    }
}

// ---------------------------------------------------------------------------
// Flash attention fp16, no-max softmax, K/V/D double-buffered, S-accum
// initialized from dist tile. grid (SEQ/128, BB*NH), 1024 thr (32 warps:
// 8 row-groups x 4 quarters). 2 barriers per kt.
// smem (halves): Qs[128][136] K2[2][64][136] V2[2][64][136] D2[2][128][72]
//                Ps[128][72] + float Lp[512]  => 161792 B
// ---------------------------------------------------------------------------
#define QSTR 136
#define PSTR 72
__global__ __launch_bounds__(1024, 1) void attn_kernel()
{
    extern __shared__ __half smh[];
    __half* Qs = smh;                    // 17408 h
    __half* K2 = Qs + 128 * QSTR;        // 2 x 8704 h
    __half* V2 = K2 + 2 * 64 * QSTR;     // 2 x 8704 h
    __half* D2 = V2 + 2 * 64 * QSTR;     // 2 x 9216 h
    __half* Ps = D2 + 2 * 128 * PSTR;    // 9216 h
    float*  Lp = (float*)(Ps + 128 * PSTR);  // 512 f

    const int tid = threadIdx.x;
    const int wid = tid >> 5, lane = tid & 31;
    const int g = lane >> 2, c = lane & 3;
    const int wm = wid & 7, wn = wid >> 3;   // 8 row-groups x 4 quarters
    const int bh = blockIdx.y;
    const int b = bh >> 3, h = bh & 7;
    const int q0 = blockIdx.x * 128;
    const int m0 = wm * 16;

    const __half* qbase = g_q + (size_t)bh * SEQ * DH;
    const __half* kbase = g_k + (size_t)bh * SEQ * DH;
    const __half* vbase = g_v + (size_t)bh * SEQ * DH;
    const __half* dbase = g_dh + ((size_t)b * SEQ + q0) * SEQ;

    const int frow = tid >> 4, fc8 = (tid & 15) * 8;   // K/V: 64 rows x 16 chunks
    const int drow = tid >> 3, dc8 = (tid & 7) * 8;    // D: 128 rows x 8 chunks

    // group A = K(kt)+D(kt); group B = V(kt)
#define FILL_A(kt) {                                                            \
        __half* Ks = K2 + ((kt) & 1) * 64 * QSTR;                               \
        __half* Ds = D2 + ((kt) & 1) * 128 * PSTR;                              \
        cpa16(&Ks[frow * QSTR + fc8],                                           \
              &kbase[(size_t)((kt) * 64 + frow) * DH + fc8]);                   \
        cpa16(&Ds[drow * PSTR + dc8],                                           \
              &dbase[(size_t)drow * SEQ + (kt) * 64 + dc8]);                    \
        CP_COMMIT(); }
#define FILL_B(kt) {                                                            \
        __half* Vs = V2 + ((kt) & 1) * 64 * QSTR;                               \
        cpa16(&Vs[frow * QSTR + fc8],                                           \
              &vbase[(size_t)((kt) * 64 + frow) * DH + fc8]);                   \
        CP_COMMIT(); }

    // prologue: A(0) = [Q + K0 + D0], then B(0) = [V0]
    {
#pragma unroll
        for (int t = 0; t < 2; t++) {
            int i = tid + t * 1024;
            int row = i >> 4, c8 = (i & 15) * 8;
            cpa16(&Qs[row * QSTR + c8], &qbase[(size_t)(q0 + row) * DH + c8]);
        }
        cpa16(&K2[frow * QSTR + fc8], &kbase[(size_t)frow * DH + fc8]);
        cpa16(&D2[drow * PSTR + dc8], &dbase[(size_t)drow * SEQ + dc8]);
        CP_COMMIT();
        FILL_B(0);
    }

    float O[4][4];
#pragma unroll
    for (int nf = 0; nf < 4; nf++)
#pragma unroll
        for (int i = 0; i < 4; i++) O[nf][i] = 0.0f;
    float l_t[2] = {0.0f, 0.0f};

    for (int kt = 0; kt < 8; kt++) {
        const __half* Ks = K2 + (kt & 1) * 64 * QSTR;
        const __half* Vs = V2 + (kt & 1) * 64 * QSTR;
        const __half* Ds = D2 + (kt & 1) * 128 * PSTR;
        CP_WAIT(1);                       // A(kt) done
        __syncthreads();                  // (also: everyone past PV(kt-1))

        // S init from dist tile (accum layout), then S += Q @ K^T
        float s[2][4];
#pragma unroll
        for (int nf = 0; nf < 2; nf++) {
            int gcol = wn * 16 + nf * 8 + 2 * c;
            float2 d0 = __half22float2(*(const __half2*)&Ds[(m0 + g) * PSTR + gcol]);
            float2 d1 = __half22float2(*(const __half2*)&Ds[(m0 + g + 8) * PSTR + gcol]);
            s[nf][0] = d0.x; s[nf][1] = d0.y;
            s[nf][2] = d1.x; s[nf][3] = d1.y;
        }
#pragma unroll
        for (int kb = 0; kb < 8; kb++) {
            const int k16 = kb * 16 + 2 * c;
            unsigned a[4];
            a[0] = *(const unsigned*)&Qs[(m0 + g) * QSTR + k16];
            a[1] = *(const unsigned*)&Qs[(m0 + g + 8) * QSTR + k16];
            a[2] = *(const unsigned*)&Qs[(m0 + g) * QSTR + k16 + 8];
            a[3] = *(const unsigned*)&Qs[(m0 + g + 8) * QSTR + k16 + 8];
#pragma unroll
            for (int nf = 0; nf < 2; nf++) {
                int col = wn * 16 + nf * 8 + g;
                unsigned bfr[2];
                bfr[0] = *(const unsigned*)&Ks[col * QSTR + k16];
                bfr[1] = *(const unsigned*)&Ks[col * QSTR + k16 + 8];
                mma16(s[nf], a, bfr);
            }
        }
        if (kt < 7) FILL_A(kt + 1);       // other buffers; no barrier needed

        // softmax: p = exp(s)   (dist+mask already inside s)
#pragma unroll
        for (int rr = 0; rr < 2; rr++) {
            const int row = m0 + g + rr * 8;
#pragma unroll
            for (int nf = 0; nf < 2; nf++) {
                int gcol = wn * 16 + nf * 8 + 2 * c;
                float p0 = __expf(s[nf][rr * 2 + 0]);
                float p1 = __expf(s[nf][rr * 2 + 1]);
                l_t[rr] += p0 + p1;
                *(__half2*)&Ps[row * PSTR + gcol] = __floats2half2_rn(p0, p1);
            }
        }
        if (kt < 7) CP_WAIT(1); else CP_WAIT(0);   // B(kt) done (A(kt+1) may pend)
        __syncthreads();                  // Ps visible; Vs ready

        // O += P @ V : 16 rows x 32 D-cols, k = 64
#pragma unroll
        for (int ks = 0; ks < 4; ks++) {
            const int k16 = ks * 16;
            unsigned a[4];
            a[0] = *(const unsigned*)&Ps[(m0 + g) * PSTR + k16 + 2 * c];
            a[1] = *(const unsigned*)&Ps[(m0 + g + 8) * PSTR + k16 + 2 * c];
            a[2] = *(const unsigned*)&Ps[(m0 + g) * PSTR + k16 + 2 * c + 8];
            a[3] = *(const unsigned*)&Ps[(m0 + g + 8) * PSTR + k16 + 2 * c + 8];
#pragma unroll
            for (int nb = 0; nb < 2; nb++) {
                unsigned v[4];
                unsigned vaddr = smaddr(&Vs[(k16 + (lane & 15)) * QSTR +
                                            wn * 32 + nb * 16 + ((lane >> 4) << 3)]);
                ldsm4t(v, vaddr);
                mma16(O[nb * 2 + 0], a, v);
                mma16(O[nb * 2 + 1], a, v + 2);
            }
        }
        if (kt < 7) FILL_B(kt + 1);       // other buffer; no barrier needed
    }

    // l: reduce over quad lanes, then over 4 quarters via smem
#pragma unroll
    for (int rr = 0; rr < 2; rr++) {
        float lv = l_t[rr];
        lv += __shfl_xor_sync(0xffffffffu, lv, 1);
        lv += __shfl_xor_sync(0xffffffffu, lv, 2);
        if (c == 0) Lp[wn * 128 + m0 + g + rr * 8] = lv;
    }
    __syncthreads();

#pragma unroll
    for (int rr = 0; rr < 2; rr++) {
        int row = m0 + g + rr * 8;
        float l = Lp[row] + Lp[128 + row] + Lp[256 + row] + Lp[384 + row];
        float inv = (l > 0.0f) ? 1.0f / l : 0.0f;
        __half* orow = g_y1h + ((size_t)b * SEQ + q0 + row) * HD + h * DH + wn * 32;
#pragma unroll
        for (int nf = 0; nf < 4; nf++) {
            int col = nf * 8 + 2 * c;
            *(__half2*)&orow[col] =
                __floats2half2_rn(O[nf][rr * 2 + 0] * inv, O[nf][rr * 2 + 1] * inv);
        }
    }
}

// ---------------------------------------------------------------------------
// Output projection fp16: out = (y1 @ Wo + bo) * mask
// grid NROWS/32 = 256, 256 thr (wm 0..1 x 16 rows, wn 0..3 x 32 cols)
// K staged 128 (8 stages), double-buf: As[32][136] + Bs(Wot)[128][136] / stage
// ---------------------------------------------------------------------------
#define OP_STG 21760
__global__ __launch_bounds__(256, 2) void oproj_kernel(
    const float* __restrict__ bo, const float* __restrict__ mask,
    float* __restrict__ out)
{
    extern __shared__ __half smh[];
    const int tid = threadIdx.x;
    const int wid = tid >> 5, lane = tid & 31;
    const int g = lane >> 2, c = lane & 3;
    const int wm = wid & 1, wn = wid >> 1;      // warp tile 16 x 32
    const int r0 = blockIdx.x * 32;
    const __half* abase = g_y1h + (size_t)r0 * HD;

    const int frow = tid >> 4, fc8 = (tid & 15) * 8;
#define OP_FILL(ks, buf) {                                                      \
        __half* As = smh + (buf) * OP_STG;                                      \
        __half* Bs = As + 4352;                                                 \
        const int k0 = (ks) * 128;                                              \
        _Pragma("unroll")                                                       \
        for (int t = 0; t < 2; t++) {                                           \
            int row = frow + t * 16;                                            \
            cpa16(&As[row * 136 + fc8], &abase[(size_t)row * HD + k0 + fc8]);   \
        }                                                                       \
        _Pragma("unroll")                                                       \
        for (int t = 0; t < 8; t++) {                                           \
            int row = frow + t * 16;                                            \
            cpa16(&Bs[row * 136 + fc8], &g_wot[(size_t)row * HD + k0 + fc8]);   \
        }                                                                       \
        CP_COMMIT(); }

    float acc[4][4];
#pragma unroll
    for (int nf = 0; nf < 4; nf++)
#pragma unroll
        for (int i = 0; i < 4; i++) acc[nf][i] = 0.0f;

    OP_FILL(0, 0);
    for (int ks = 0; ks < 8; ks++) {
        if (ks < 7) { OP_FILL(ks + 1, (ks + 1) & 1); CP_WAIT(1); }
        else        { CP_WAIT(0); }
        __syncthreads();
        const __half* As = smh + (ks & 1) * OP_STG;
        const __half* Bs = As + 4352;
#pragma unroll
        for (int kb = 0; kb < 8; kb++) {
            const int k16 = kb * 16 + 2 * c;
            unsigned a[4];
            int row = wm * 16;
            a[0] = *(const unsigned*)&As[(row + g) * 136 + k16];
            a[1] = *(const unsigned*)&As[(row + g + 8) * 136 + k16];
            a[2] = *(const unsigned*)&As[(row + g) * 136 + k16 + 8];
            a[3] = *(const unsigned*)&As[(row + g + 8) * 136 + k16 + 8];
#pragma unroll
            for (int nf = 0; nf < 4; nf++) {
                int col = wn * 32 + nf * 8;
                unsigned b[2];
                b[0] = *(const unsigned*)&Bs[(col + g) * 136 + k16];
                b[1] = *(const unsigned*)&Bs[(col + g) * 136 + k16 + 8];
                mma16(acc[nf], a, b);
            }
        }
        __syncthreads();
    }

#pragma unroll
    for (int rr = 0; rr < 2; rr++) {
        int row = r0 + wm * 16 + g + rr * 8;
        float mm = mask[row];
#pragma unroll
        for (int nf = 0; nf < 4; nf++) {
            int col = wn * 32 + nf * 8 + 2 * c;
            float v0 = (acc[nf][rr * 2 + 0] + bo[col]) * mm;
            float v1 = (acc[nf][rr * 2 + 1] + bo[col + 1]) * mm;
            *(float2*)&out[(size_t)row * DH + col] = make_float2(v0, v1);
        }
    }
}

// ---------------------------------------------------------------------------
extern "C" void kernel_launch(void* const* d_in, const int* in_sizes, int n_in,
                              void* d_out, int out_size)
{
    const float* x    = (const float*)d_in[0];
    const float* dist = (const float*)d_in[1];
    const float* mask = (const float*)d_in[2];
    const float* Wq   = (const float*)d_in[3];
    const float* bq   = (const float*)d_in[4];
    const float* Wk   = (const float*)d_in[5];
    const float* bk   = (const float*)d_in[6];
    const float* Wv   = (const float*)d_in[7];
    const float* bv   = (const float*)d_in[8];
    const float* Wo   = (const float*)d_in[9];
    const float* bo   = (const float*)d_in[10];
    float* out = (float*)d_out;

    const int proj_smem = PROJ_STG * 2 * 2;                            // 73728
    const int attn_smem = (17408 + 2*8704 + 2*8704 + 2*9216 + 9216) * 2 + 512 * 4; // 161792
    const int op_smem   = OP_STG * 2 * 2;                              // 87040
    static int configured = 0;
    if (!configured) {
        cudaFuncSetAttribute(proj_kernel, cudaFuncAttributeMaxDynamicSharedMemorySize, proj_smem);
        cudaFuncSetAttribute(attn_kernel, cudaFuncAttributeMaxDynamicSharedMemorySize, attn_smem);
        cudaFuncSetAttribute(oproj_kernel, cudaFuncAttributeMaxDynamicSharedMemorySize, op_smem);
        configured = 1;
    }

    prep_kernel<<<1024, 256>>>(x);
    wtrans_kernel<<<dim3(32, 32, 4), dim3(32, 8)>>>(Wq, Wk, Wv, Wo);
    dprep_kernel<<<4096, 256>>>(dist, mask);
    proj_kernel<<<dim3(HD/128, NROWS/128, 3), 256, proj_smem>>>(mask, bq, bk, bv);
    attn_kernel<<<dim3(SEQ/128, BB*NH), 1024, attn_smem>>>();
    oproj_kernel<<<dim3(NROWS/32), 256, op_smem>>>(bo, mask, out);
}